// round 15
// baseline (speedup 1.0000x reference)
#include <cuda_runtime.h>
#include <cuda_fp16.h>
#include <cstdint>

#define M_TOTAL 8192
#define N_TOTAL 4096
#define K_TOTAL 4096

// Fragment-major operand layouts (PTX mma.m16n8k16 register layouts),
// written by prep, consumed by direct LDG.128 in the GEMM (no smem at all).
//   A: [M/16][K/16][lane][uint4]  (a0..a3 for one m16k16 tile)
//   B: [N/8][K/32][lane][uint4]   (b0,b1 for k16-lo | b0,b1 for k16-hi)
__device__ uint4 g_Afrag[(size_t)(M_TOTAL / 16) * (K_TOTAL / 16) * 32];  // 64 MB
__device__ uint4 g_Bfrag[(size_t)(N_TOTAL / 8) * (K_TOTAL / 32) * 32];   // 32 MB

#define A_BLOCKS ((M_TOTAL / 16) * (K_TOTAL / 16) * 32 / 256)   // 16384
#define B_BLOCKS ((N_TOTAL / 8) * (K_TOTAL / 32) * 32 / 256)    // 8192

__device__ __forceinline__ uint32_t h2pack(float a, float b) {
    __half2 h = __floats2half2_rn(a, b);
    return *(uint32_t*)&h;
}

// ---------------------------------------------------------------------------
// Fused prep: convert x (fp32) and wq (int32) into fragment-major fp16.
// ---------------------------------------------------------------------------
__global__ void __launch_bounds__(256) prep_kernel(const float* __restrict__ x,
                                                   const int* __restrict__ wq) {
    size_t gid = (size_t)blockIdx.x * 256 + threadIdx.x;
    if (blockIdx.x < A_BLOCKS) {
        uint32_t lane  = (uint32_t)gid & 31;
        uint32_t ktile = ((uint32_t)(gid >> 5)) & 255;
        uint32_t mtile = (uint32_t)(gid >> 13);
        uint32_t r  = lane >> 2;
        uint32_t c0 = (lane & 3) * 2;
        const float2* x2 = (const float2*)x;
        size_t row0 = (size_t)(mtile * 16 + r) * (K_TOTAL / 2);
        size_t row1 = row0 + 8 * (K_TOTAL / 2);
        uint32_t colh = (ktile * 16 + c0) >> 1;
        float2 f0 = x2[row0 + colh];
        float2 f1 = x2[row1 + colh];
        float2 f2 = x2[row0 + colh + 4];
        float2 f3 = x2[row1 + colh + 4];
        uint4 o;
        o.x = h2pack(f0.x, f0.y);
        o.y = h2pack(f1.x, f1.y);
        o.z = h2pack(f2.x, f2.y);
        o.w = h2pack(f3.x, f3.y);
        g_Afrag[gid] = o;
    } else {
        size_t j = gid - (size_t)A_BLOCKS * 256;
        uint32_t lane  = (uint32_t)j & 31;
        uint32_t kt32  = ((uint32_t)(j >> 5)) & 127;
        uint32_t ntile = (uint32_t)(j >> 12);
        uint32_t g = lane >> 2;
        uint32_t t = lane & 3;
        const int2* w2 = (const int2*)wq;
        size_t rowb = (size_t)(ntile * 8 + g) * (K_TOTAL / 2);
        uint32_t kh = (kt32 * 32 + t * 2) >> 1;
        int2 p0 = w2[rowb + kh];
        int2 p1 = w2[rowb + kh + 4];
        int2 p2 = w2[rowb + kh + 8];
        int2 p3 = w2[rowb + kh + 12];
        uint4 o;
        o.x = h2pack((float)p0.x, (float)p0.y);
        o.y = h2pack((float)p1.x, (float)p1.y);
        o.z = h2pack((float)p2.x, (float)p2.y);
        o.w = h2pack((float)p3.x, (float)p3.y);
        g_Bfrag[j] = o;
    }
}

// ---------------------------------------------------------------------------
__device__ __forceinline__ void mma_fr(float* c, uint4 a, uint32_t b0, uint32_t b1) {
    asm volatile(
        "mma.sync.aligned.m16n8k16.row.col.f32.f16.f16.f32 "
        "{%0,%1,%2,%3}, {%4,%5,%6,%7}, {%8,%9}, {%0,%1,%2,%3};\n"
        : "+f"(c[0]), "+f"(c[1]), "+f"(c[2]), "+f"(c[3])
        : "r"(a.x), "r"(a.y), "r"(a.z), "r"(a.w), "r"(b0), "r"(b1));
}
__device__ __forceinline__ void pref_l1(const void* p) {
    asm volatile("prefetch.global.L1 [%0];" :: "l"(p));
}

// ---------------------------------------------------------------------------
// GEMM with ZERO shared memory, ZERO barriers, and warp-wide L1 prefetch.
// CTA 128x128, 8 warps (2M x 4N), warp tile 64x32. 2 CTAs/SM (regs 126).
// Prefetch: 2 warp-wide prefetch.global.L1 per iter cover all 48 lines
// (12 blocks x 512B) of iteration kt+2's operands — zero register cost,
// converting per-iter first-reader L2 hits (~250cyc) into L1 hits (~39cyc).
// ---------------------------------------------------------------------------
#define KT16_STRIDE_A 32            // uint4 per kt16 step within one m-tile
#define MT_STRIDE_A   (256 * 32)    // uint4 per m16 tile (K/16=256 ktiles)
#define KT32_STRIDE_B 32
#define NT_STRIDE_B   (128 * 32)    // uint4 per n8 tile (K/32=128)
#define PF 2                        // prefetch distance (k32 iterations)

__global__ void __launch_bounds__(256, 2)
gemm_kernel(const float* __restrict__ wscale, const float* __restrict__ bias,
            float* __restrict__ out)
{
    const int tid  = threadIdx.x;
    const int lane = tid & 31;
    const int warp = tid >> 5;
    const int wm   = warp >> 2;   // 0..1
    const int wn   = warp & 3;    // 0..3
    const int bm   = blockIdx.y * 128;
    const int bn   = blockIdx.x * 128;

    const int mt0 = (bm >> 4) + wm * 4;   // 4 consecutive m16 tiles
    const int nt0 = (bn >> 3) + wn * 4;   // 4 consecutive n8 tiles

    const uint4* __restrict__ pA = g_Afrag + (size_t)mt0 * MT_STRIDE_A + lane;
    const uint4* __restrict__ pB = g_Bfrag + (size_t)nt0 * NT_STRIDE_B + lane;

    // ---- warp-wide prefetch lane mapping (loop-invariant offsets)
    // A: 8 blocks (f=lane>>3, h=(lane>>2)&1), 4 lines each (lane&3)
    const char* prefA = (const char*)(g_Afrag + (size_t)mt0 * MT_STRIDE_A)
                      + (size_t)(lane >> 3) * (MT_STRIDE_A * 16)
                      + (size_t)((lane >> 2) & 1) * 512
                      + (size_t)(lane & 3) * 128;
    // B: 4 blocks (g), 4 lines each; lanes 16-31 duplicate lanes 0-15
    const int laneB = lane & 15;
    const char* prefB = (const char*)(g_Bfrag + (size_t)nt0 * NT_STRIDE_B)
                      + (size_t)(laneB >> 2) * (NT_STRIDE_B * 16)
                      + (size_t)(laneB & 3) * 128;

    // warm the first PF iterations
    #pragma unroll
    for (int p = 0; p < PF; p++) {
        pref_l1(prefA + (size_t)p * 1024);
        pref_l1(prefB + (size_t)p * 512);
    }
    prefA += (size_t)PF * 1024;
    prefB += (size_t)PF * 512;

    float acc[4][4][4];
    #pragma unroll
    for (int f = 0; f < 4; f++)
        #pragma unroll
        for (int g = 0; g < 4; g++)
            #pragma unroll
            for (int e = 0; e < 4; e++) acc[f][g][e] = 0.f;

    #pragma unroll 1
    for (int kt = 0; kt < K_TOTAL / 32; kt++) {
        // B fragments for both k16 halves of this k32 (4 n8 tiles)
        uint4 b0 = pB[0 * NT_STRIDE_B];
        uint4 b1 = pB[1 * NT_STRIDE_B];
        uint4 b2 = pB[2 * NT_STRIDE_B];
        uint4 b3 = pB[3 * NT_STRIDE_B];
        // A fragments, k16-lo
        uint4 a0 = pA[0 * MT_STRIDE_A];
        uint4 a1 = pA[1 * MT_STRIDE_A];
        uint4 a2 = pA[2 * MT_STRIDE_A];
        uint4 a3 = pA[3 * MT_STRIDE_A];

        // prefetch iteration kt+PF (all 48 lines, 2 warp-wide ops, 0 regs)
        pref_l1(prefA);  prefA += 1024;
        pref_l1(prefB);  prefB += 512;

        mma_fr(acc[0][0], a0, b0.x, b0.y); mma_fr(acc[0][1], a0, b1.x, b1.y);
        mma_fr(acc[0][2], a0, b2.x, b2.y); mma_fr(acc[0][3], a0, b3.x, b3.y);
        mma_fr(acc[1][0], a1, b0.x, b0.y); mma_fr(acc[1][1], a1, b1.x, b1.y);
        mma_fr(acc[1][2], a1, b2.x, b2.y); mma_fr(acc[1][3], a1, b3.x, b3.y);
        mma_fr(acc[2][0], a2, b0.x, b0.y); mma_fr(acc[2][1], a2, b1.x, b1.y);
        mma_fr(acc[2][2], a2, b2.x, b2.y); mma_fr(acc[2][3], a2, b3.x, b3.y);
        mma_fr(acc[3][0], a3, b0.x, b0.y); mma_fr(acc[3][1], a3, b1.x, b1.y);
        mma_fr(acc[3][2], a3, b2.x, b2.y); mma_fr(acc[3][3], a3, b3.x, b3.y);

        // A fragments, k16-hi (reuse registers)
        a0 = pA[0 * MT_STRIDE_A + KT16_STRIDE_A];
        a1 = pA[1 * MT_STRIDE_A + KT16_STRIDE_A];
        a2 = pA[2 * MT_STRIDE_A + KT16_STRIDE_A];
        a3 = pA[3 * MT_STRIDE_A + KT16_STRIDE_A];

        mma_fr(acc[0][0], a0, b0.z, b0.w); mma_fr(acc[0][1], a0, b1.z, b1.w);
        mma_fr(acc[0][2], a0, b2.z, b2.w); mma_fr(acc[0][3], a0, b3.z, b3.w);
        mma_fr(acc[1][0], a1, b0.z, b0.w); mma_fr(acc[1][1], a1, b1.z, b1.w);
        mma_fr(acc[1][2], a1, b2.z, b2.w); mma_fr(acc[1][3], a1, b3.z, b3.w);
        mma_fr(acc[2][0], a2, b0.z, b0.w); mma_fr(acc[2][1], a2, b1.z, b1.w);
        mma_fr(acc[2][2], a2, b2.z, b2.w); mma_fr(acc[2][3], a2, b3.z, b3.w);
        mma_fr(acc[3][0], a3, b0.z, b0.w); mma_fr(acc[3][1], a3, b1.z, b1.w);
        mma_fr(acc[3][2], a3, b2.z, b2.w); mma_fr(acc[3][3], a3, b3.z, b3.w);

        pA += 2 * KT16_STRIDE_A;   // advance one k32
        pB += KT32_STRIDE_B;
    }

    // ---- epilogue: out = scale[n]*acc + bias[n]
    const int mrow  = bm + wm * 64 + (lane >> 2);
    const int ncol0 = bn + wn * 32 + (lane & 3) * 2;

    #pragma unroll
    for (int f = 0; f < 4; f++) {
        int r0 = mrow + f * 16;
        #pragma unroll
        for (int g = 0; g < 4; g++) {
            int col = ncol0 + g * 8;
            float sx = wscale[col], sy = wscale[col + 1];
            float bx = bias[col],   by = bias[col + 1];
            float2 v0, v1;
            v0.x = acc[f][g][0] * sx + bx;
            v0.y = acc[f][g][1] * sy + by;
            v1.x = acc[f][g][2] * sx + bx;
            v1.y = acc[f][g][3] * sy + by;
            *(float2*)(out + (size_t)r0 * N_TOTAL + col)       = v0;
            *(float2*)(out + (size_t)(r0 + 8) * N_TOTAL + col) = v1;
        }
    }
}

// ---------------------------------------------------------------------------
extern "C" void kernel_launch(void* const* d_in, const int* in_sizes, int n_in,
                              void* d_out, int out_size) {
    const float* x      = (const float*)d_in[0];
    const int*   wq     = (const int*)d_in[1];
    const float* wscale = (const float*)d_in[2];
    const float* bias   = (const float*)d_in[3];
    float*       out    = (float*)d_out;

    prep_kernel<<<A_BLOCKS + B_BLOCKS, 256>>>(x, wq);

    // No shared memory: give the whole carveout to L1 (fragment reuse cache).
    cudaFuncSetAttribute(gemm_kernel, cudaFuncAttributePreferredSharedMemoryCarveout,
                         cudaSharedmemCarveoutMaxL1);
    dim3 grid(N_TOTAL / 128, M_TOTAL / 128);   // N fastest for B reuse in L2
    gemm_kernel<<<grid, 256>>>(wscale, bias, out);
}

// round 17
// speedup vs baseline: 1.2964x; 1.2964x over previous
#include <cuda_runtime.h>
#include <cuda_fp16.h>
#include <cstdint>

#define M_TOTAL 8192
#define N_TOTAL 4096
#define K_TOTAL 4096

// fp16 operands: A = fp16(x) [M][K], B = exact int4 values in fp16 [N][K]
__device__ __half g_A[(size_t)M_TOTAL * K_TOTAL];   // 64 MB
__device__ __half g_B[(size_t)N_TOTAL * K_TOTAL];   // 32 MB

// ---------------------------------------------------------------------------
// Fused prep kernel: A-convert chunks first, then B-convert chunks.
// ---------------------------------------------------------------------------
#define NA_CHUNKS ((size_t)M_TOTAL * K_TOTAL / 4)
#define NB_CHUNKS ((size_t)N_TOTAL * K_TOTAL / 4)

__global__ void __launch_bounds__(256) prep_kernel(const float4* __restrict__ x4,
                                                   const int4* __restrict__ w4) {
    size_t i = (size_t)blockIdx.x * 256 + threadIdx.x;
    if (i < NA_CHUNKS) {
        float4 v = x4[i];
        __half2* dst = (__half2*)g_A + i * 2;
        dst[0] = __floats2half2_rn(v.x, v.y);
        dst[1] = __floats2half2_rn(v.z, v.w);
    } else {
        size_t j = i - NA_CHUNKS;
        int4 q = w4[j];
        __half2* dst = (__half2*)g_B + j * 2;
        dst[0] = __floats2half2_rn((float)q.x, (float)q.y);
        dst[1] = __floats2half2_rn((float)q.z, (float)q.w);
    }
}

// ---------------------------------------------------------------------------
// Helpers
// ---------------------------------------------------------------------------
__device__ __forceinline__ uint32_t smem_u32(const void* p) {
    uint32_t a;
    asm("{ .reg .u64 t; cvta.to.shared.u64 t, %1; cvt.u32.u64 %0, t; }" : "=r"(a) : "l"(p));
    return a;
}
__device__ __forceinline__ void cp_async16(uint32_t dst, const void* src) {
    asm volatile("cp.async.cg.shared.global [%0], [%1], 16;\n" :: "r"(dst), "l"(src));
}
__device__ __forceinline__ void ldm_x4(uint32_t& d0, uint32_t& d1, uint32_t& d2, uint32_t& d3, uint32_t a) {
    asm volatile("ldmatrix.sync.aligned.m8n8.x4.shared.b16 {%0,%1,%2,%3}, [%4];\n"
                 : "=r"(d0), "=r"(d1), "=r"(d2), "=r"(d3) : "r"(a));
}
__device__ __forceinline__ void mma16816(float* c, const uint32_t* a, uint32_t b0, uint32_t b1) {
    asm volatile(
        "mma.sync.aligned.m16n8k16.row.col.f32.f16.f16.f32 "
        "{%0,%1,%2,%3}, {%4,%5,%6,%7}, {%8,%9}, {%0,%1,%2,%3};\n"
        : "+f"(c[0]), "+f"(c[1]), "+f"(c[2]), "+f"(c[3])
        : "r"(a[0]), "r"(a[1]), "r"(a[2]), "r"(a[3]), "r"(b0), "r"(b1));
}

// ---------------------------------------------------------------------------
// GEMM: CTA 128x128, BK=64, 3-stage cp.async ring, 8 warps (2M x 4N),
// warp tile 64x32. 97KB smem/CTA + carveout=100 + minBlocks=2 -> 2 CTAs/SM.
// Measured optimum of the mma.sync design space (R12: tensor 75.5%, regs 126):
// the L1/shared port (128 B/cyc) and tensor pipe are co-saturated, and every
// alternative (bigger warp tiles, 3 CTAs/SM, smem-free fragments, prefetch)
// measured worse. Byte-exact revert to R12.
// ---------------------------------------------------------------------------
#define BK 64
#define STAGES 3
#define NITER (K_TOTAL / BK)     // 64
#define OP_STAGE 16384           // 128 rows x 128 B per operand
#define SMEM_BYTES (2 * STAGES * OP_STAGE + 1024)   // 99328

__global__ void __launch_bounds__(256, 2)
gemm_kernel(const float* __restrict__ wscale, const float* __restrict__ bias,
            float* __restrict__ out)
{
    extern __shared__ char smem_raw[];
    const uint32_t base = (smem_u32(smem_raw) + 1023u) & ~1023u;
    const uint32_t sAb = base;                          // 3 x 16 KB
    const uint32_t sBb = base + STAGES * OP_STAGE;      // 3 x 16 KB

    const int tid  = threadIdx.x;
    const int lane = tid & 31;
    const int warp = tid >> 5;
    const int wm   = warp >> 2;   // 0..1
    const int wn   = warp & 3;    // 0..3
    const int bm   = blockIdx.y * 128;
    const int bn   = blockIdx.x * 128;

    // ---- producer mapping: per operand per stage, 4 rows x 16B per thread
    const int pr = tid >> 3;           // 0..31
    const int kc = tid & 7;
    const uint32_t pswz = (uint32_t)(pr & 7);
    uint32_t soff[4];
    #pragma unroll
    for (int j = 0; j < 4; j++)
        soff[j] = (uint32_t)(pr + 32 * j) * 128 + (((uint32_t)kc ^ pswz) << 4);

    const __half* gA = g_A + (size_t)(bm + pr) * K_TOTAL + kc * 8;
    const __half* gB = g_B + (size_t)(bn + pr) * K_TOTAL + kc * 8;

    // ---- A ldmatrix (x4, m16k16): f -> m row wm*64 + f*16 + (lane&15)
    const int a_kg = lane >> 4;
    uint32_t a_off[4], a_sw[4];
    #pragma unroll
    for (int f = 0; f < 4; f++) {
        int row = wm * 64 + f * 16 + (lane & 15);
        a_off[f] = (uint32_t)row * 128;
        a_sw[f]  = (uint32_t)(row & 7);
    }
    // ---- B ldmatrix (x4 covering n16 x k16)
    const int b_kc2 = (lane >> 3) & 1;
    const int b_rowb = (lane & 7) + ((lane >> 4) << 3);
    uint32_t b_off[2], b_sw[2];
    #pragma unroll
    for (int g2 = 0; g2 < 2; g2++) {
        int row = wn * 32 + g2 * 16 + b_rowb;
        b_off[g2] = (uint32_t)row * 128;
        b_sw[g2]  = (uint32_t)(row & 7);
    }

    float acc[4][4][4];
    #pragma unroll
    for (int f = 0; f < 4; f++)
        #pragma unroll
        for (int g = 0; g < 4; g++)
            #pragma unroll
            for (int e = 0; e < 4; e++) acc[f][g][e] = 0.f;

    // ---- prologue: fill STAGES-1 slots
    #pragma unroll
    for (int s = 0; s < STAGES - 1; s++) {
        const uint32_t dA = sAb + s * OP_STAGE;
        const uint32_t dB = sBb + s * OP_STAGE;
        const int k = s * BK;
        #pragma unroll
        for (int j = 0; j < 4; j++) {
            cp_async16(dA + soff[j], gA + (size_t)(32 * j) * K_TOTAL + k);
            cp_async16(dB + soff[j], gB + (size_t)(32 * j) * K_TOTAL + k);
        }
        asm volatile("cp.async.commit_group;\n" ::: "memory");
    }

    // rolling ring indices: rslot = consume slot, pslot = prefetch slot
    uint32_t rOffA = 0, pOffA = (uint32_t)(STAGES - 1) * OP_STAGE;
    int pk = (STAGES - 1) * BK;   // next k to prefetch

    for (int kt = 0; kt < NITER; kt++) {
        asm volatile("cp.async.wait_group %0;\n" :: "n"(STAGES - 2) : "memory");
        __syncthreads();

        if (pk < K_TOTAL) {
            const uint32_t dA = sAb + pOffA;
            const uint32_t dB = sBb + pOffA;
            #pragma unroll
            for (int j = 0; j < 4; j++) {
                cp_async16(dA + soff[j], gA + (size_t)(32 * j) * K_TOTAL + pk);
                cp_async16(dB + soff[j], gB + (size_t)(32 * j) * K_TOTAL + pk);
            }
            pk += BK;
            pOffA += OP_STAGE;
            if (pOffA == STAGES * OP_STAGE) pOffA = 0;
        }
        asm volatile("cp.async.commit_group;\n" ::: "memory");

        const uint32_t sAbuf = sAb + rOffA;
        const uint32_t sBbuf = sBb + rOffA;
        rOffA += OP_STAGE;
        if (rOffA == STAGES * OP_STAGE) rOffA = 0;

        #pragma unroll
        for (int ks = 0; ks < 4; ks++) {        // 4 x k16 within the 64-k tile
            uint32_t a[4][4];
            #pragma unroll
            for (int f = 0; f < 4; f++) {
                uint32_t chunk = (uint32_t)(ks * 2 + a_kg) ^ a_sw[f];
                ldm_x4(a[f][0], a[f][1], a[f][2], a[f][3],
                       sAbuf + a_off[f] + (chunk << 4));
            }
            uint32_t b[2][4];
            #pragma unroll
            for (int g2 = 0; g2 < 2; g2++) {
                uint32_t chunk = (uint32_t)(ks * 2 + b_kc2) ^ b_sw[g2];
                ldm_x4(b[g2][0], b[g2][1], b[g2][2], b[g2][3],
                       sBbuf + b_off[g2] + (chunk << 4));
            }
            #pragma unroll
            for (int f = 0; f < 4; f++) {
                #pragma unroll
                for (int g2 = 0; g2 < 2; g2++) {
                    mma16816(acc[f][g2 * 2 + 0], a[f], b[g2][0], b[g2][1]);
                    mma16816(acc[f][g2 * 2 + 1], a[f], b[g2][2], b[g2][3]);
                }
            }
        }
    }

    // ---- epilogue: out = scale[n]*acc + bias[n]
    const int mrow  = bm + wm * 64 + (lane >> 2);
    const int ncol0 = bn + wn * 32 + (lane & 3) * 2;

    #pragma unroll
    for (int f = 0; f < 4; f++) {
        int r0 = mrow + f * 16;
        #pragma unroll
        for (int g = 0; g < 4; g++) {
            int col = ncol0 + g * 8;
            float sx = wscale[col], sy = wscale[col + 1];
            float bx = bias[col],   by = bias[col + 1];
            float2 v0, v1;
            v0.x = acc[f][g][0] * sx + bx;
            v0.y = acc[f][g][1] * sy + by;
            v1.x = acc[f][g][2] * sx + bx;
            v1.y = acc[f][g][3] * sy + by;
            *(float2*)(out + (size_t)r0 * N_TOTAL + col)       = v0;
            *(float2*)(out + (size_t)(r0 + 8) * N_TOTAL + col) = v1;
        }
    }
}

// ---------------------------------------------------------------------------
extern "C" void kernel_launch(void* const* d_in, const int* in_sizes, int n_in,
                              void* d_out, int out_size) {
    const float* x      = (const float*)d_in[0];
    const int*   wq     = (const int*)d_in[1];
    const float* wscale = (const float*)d_in[2];
    const float* bias   = (const float*)d_in[3];
    float*       out    = (float*)d_out;

    prep_kernel<<<(NA_CHUNKS + NB_CHUNKS) / 256, 256>>>((const float4*)x, (const int4*)wq);

    cudaFuncSetAttribute(gemm_kernel, cudaFuncAttributeMaxDynamicSharedMemorySize, SMEM_BYTES);
    // Full 228KB carveout so TWO 97KB CTAs co-reside per SM (16 warps/SM).
    cudaFuncSetAttribute(gemm_kernel, cudaFuncAttributePreferredSharedMemoryCarveout, 100);
    dim3 grid(N_TOTAL / 128, M_TOTAL / 128);   // N fastest for B reuse in L2
    gemm_kernel<<<grid, 256, SMEM_BYTES>>>(wscale, bias, out);
}